// round 15
// baseline (speedup 1.0000x reference)
#include <cuda_runtime.h>
#include <math.h>
#include <stdint.h>

// BitNet MoE layer, GB300.  R15: block-specialized hybrid GEMMs.  The
// intra-block hybrid (R13/R14) was barrier-coupling-bound (~40%/23% pipes,
// nothing saturated).  Now each block is homogeneous: grid-y = 64-col
// N-tiles, path = (bx^by)&1 -> even blocks run the R10-proven mma.sync core,
// odd blocks the R4-proven dp4a core.  The SM scheduler co-residents both
// flavors -> tensor + fma pipes overlap with NO shared barrier.  Exact
// 50/50 work split per row-tile; engines measured equal (~256 MAC/cyc/SM).

#define TOK  8192
#define HD   768
#define ID   2048
#define NEXP 9
#define NMAT 27
#define NW   (ID*HD)
#define RED_BLK 64

// ---------------- scratch (device globals; allocation-free) ----------------
__device__ __align__(16) int8_t g_qw[3][NEXP][NW];            // {-1,0,1}
__device__ double g_part[NMAT * RED_BLK * 2];
__device__ float  g_wscale[NMAT];
__device__ float  g_logits_scratch[TOK * 8];
__device__ int    g_cnt[NEXP];                                 // re-zeroed by k_clip
__device__ int    g_lidx[NEXP * TOK];
__device__ float  g_lw[NEXP * TOK];
__device__ __align__(16) int8_t g_xg[(size_t)NEXP * TOK * HD];
__device__ __align__(16) int8_t g_xu[(size_t)NEXP * TOK * HD];
__device__ float  g_ag[NEXP * TOK], g_au[NEXP * TOK], g_ah[NEXP * TOK];
__device__ __align__(16) float  g_hidden[(size_t)NEXP * TOK * ID];
__device__ __align__(16) int8_t g_hq[(size_t)NEXP * TOK * ID];

__device__ __forceinline__ float clipf(float v, float lo, float hi) {
    return fminf(fmaxf(v, lo), hi);
}

__device__ __forceinline__ float fast_sigmoid(float g) {
    float ax = fabsf(g);
    float z  = -1.4426950408889634f * ax;
    float nf = rintf(z);
    float f  = z - nf;
    float p  = 1.5403530e-4f;
    p = fmaf(p, f, 1.33335581e-3f);
    p = fmaf(p, f, 9.61812911e-3f);
    p = fmaf(p, f, 5.55041087e-2f);
    p = fmaf(p, f, 2.40226507e-1f);
    p = fmaf(p, f, 6.93147181e-1f);
    p = fmaf(p, f, 1.0f);
    float s = __int_as_float(((int)nf + 127) << 23);
    float t = p * s;
    float d = 1.0f + t;
    float r = __int_as_float(0x7EF311C3 - __float_as_int(d));
    r = r * (2.0f - d * r);
    r = r * (2.0f - d * r);
    r = r * (2.0f - d * r);
    return (g >= 0.f) ? r : 1.0f - r;
}

__device__ __forceinline__ uint32_t smem_u32(const void* p) {
    uint32_t a;
    asm("{ .reg .u64 t; cvta.to.shared.u64 t, %1; cvt.u32.u64 %0, t; }"
        : "=r"(a) : "l"(p));
    return a;
}
__device__ __forceinline__ void cpa16(uint32_t dst, const void* src) {
    asm volatile("cp.async.cg.shared.global [%0], [%1], 16;"
                 :: "r"(dst), "l"(src) : "memory");
}
#define CP_COMMIT() asm volatile("cp.async.commit_group;" ::: "memory")
#define CP_WAIT_1() asm volatile("cp.async.wait_group 1;" ::: "memory")

__device__ __forceinline__ void mma_s8(int* c, const int* a, const int* b) {
    asm volatile(
        "mma.sync.aligned.m16n8k32.row.col.s32.s8.s8.s32 "
        "{%0,%1,%2,%3}, {%4,%5,%6,%7}, {%8,%9}, {%0,%1,%2,%3};"
        : "+r"(c[0]), "+r"(c[1]), "+r"(c[2]), "+r"(c[3])
        : "r"(a[0]), "r"(a[1]), "r"(a[2]), "r"(a[3]), "r"(b[0]), "r"(b[1]));
}
__device__ __forceinline__ void load_a_frag(int* a, const uint8_t* smem_row0,
                                            int lane) {
    const uint8_t* p = smem_row0 + (lane >> 2) * 80 + (lane & 3) * 4;
    a[0] = *(const int*)(p);
    a[1] = *(const int*)(p + 8 * 80);
    a[2] = *(const int*)(p + 16);
    a[3] = *(const int*)(p + 8 * 80 + 16);
}
__device__ __forceinline__ void load_b_frag(int* b, const uint8_t* smem_row0,
                                            int lane) {
    const uint8_t* p = smem_row0 + (lane >> 2) * 80 + (lane & 3) * 4;
    b[0] = *(const int*)(p);
    b[1] = *(const int*)(p + 16);
}
__device__ __forceinline__ int dp4(int4 a, int4 b, int c) {
    c = __dp4a(a.x, b.x, c);
    c = __dp4a(a.y, b.y, c);
    c = __dp4a(a.z, b.z, c);
    c = __dp4a(a.w, b.w, c);
    return c;
}

// ---------------- k_pre: weight reductions + router/top2 (fused) ----------
__global__ __launch_bounds__(256) void k_pre(
    const float* __restrict__ x,  const float* __restrict__ rw,
    const float* __restrict__ rb, float* __restrict__ logits_out,
    float* __restrict__ out,
    const float* __restrict__ Wg, const float* __restrict__ Wu,
    const float* __restrict__ Wd, const float* __restrict__ sWg,
    const float* __restrict__ sWu, const float* __restrict__ sWd) {
    int b = blockIdx.x, tid = threadIdx.x;
    if (b < RED_BLK * NMAT) {
        int m = b / RED_BLK, bx = b % RED_BLK;
        int kind = m / NEXP, e = m % NEXP;
        const float* base =
            (kind == 0) ? ((e < 8) ? Wg + (size_t)e * NW : sWg)
          : (kind == 1) ? ((e < 8) ? Wu + (size_t)e * NW : sWu)
                        : ((e < 8) ? Wd + (size_t)e * NW : sWd);
        const float4* w4 = (const float4*)base;
        const int N4 = NW / 4;
        float s = 0.f, a = 0.f;
        for (int i = bx * 256 + tid; i < N4; i += RED_BLK * 256) {
            float4 v = w4[i];
            s += (v.x + v.y) + (v.z + v.w);
            a += (fabsf(v.x) + fabsf(v.y)) + (fabsf(v.z) + fabsf(v.w));
        }
        __shared__ double ss[256], sa[256];
        ss[tid] = (double)s; sa[tid] = (double)a;
        __syncthreads();
        for (int o = 128; o; o >>= 1) {
            if (tid < o) { ss[tid] += ss[tid + o]; sa[tid] += sa[tid + o]; }
            __syncthreads();
        }
        if (tid == 0) {
            g_part[(m * RED_BLK + bx) * 2 + 0] = ss[0];
            g_part[(m * RED_BLK + bx) * 2 + 1] = sa[0];
        }
        return;
    }
    int t = b - RED_BLK * NMAT;
    for (int j = tid; j < HD; j += 256) out[(size_t)t * HD + j] = 0.f;
    const float* xr = x + (size_t)t * HD;
    float acc[8];
#pragma unroll
    for (int e = 0; e < 8; e++) acc[e] = 0.f;
    for (int h = tid; h < HD; h += 256) {
        float xv = xr[h];
#pragma unroll
        for (int e = 0; e < 8; e++) acc[e] += xv * rw[e * HD + h];
    }
    __shared__ float s2[8][256];
#pragma unroll
    for (int e = 0; e < 8; e++) s2[e][tid] = acc[e];
    __syncthreads();
    for (int o = 128; o; o >>= 1) {
        if (tid < o) {
#pragma unroll
            for (int e = 0; e < 8; e++) s2[e][tid] += s2[e][tid + o];
        }
        __syncthreads();
    }
    if (tid == 0) {
        float l[8], p[8];
        float mx = -1e30f;
#pragma unroll
        for (int e = 0; e < 8; e++) {
            l[e] = s2[e][0] + rb[e];
            logits_out[t * 8 + e] = l[e];
            mx = fmaxf(mx, l[e]);
        }
        float ps = 0.f;
#pragma unroll
        for (int e = 0; e < 8; e++) { p[e] = expf(l[e] - mx); ps += p[e]; }
#pragma unroll
        for (int e = 0; e < 8; e++) p[e] /= ps;
        int i1 = 0;
#pragma unroll
        for (int e = 1; e < 8; e++) if (p[e] > p[i1]) i1 = e;
        int i2 = -1;
#pragma unroll
        for (int e = 0; e < 8; e++) {
            if (e == i1) continue;
            if (i2 < 0 || p[e] > p[i2]) i2 = e;
        }
        float den = p[i1] + p[i2] + 1e-8f;
        int p1 = atomicAdd(&g_cnt[i1], 1);
        g_lidx[i1 * TOK + p1] = t;
        g_lw[i1 * TOK + p1] = p[i1] / den;
        int p2 = atomicAdd(&g_cnt[i2], 1);
        g_lidx[i2 * TOK + p2] = t;
        g_lw[i2 * TOK + p2] = p[i2] / den;
        g_lidx[8 * TOK + t] = t;
        g_lw[8 * TOK + t] = 1.f;
        if (t == 0) g_cnt[8] = TOK;
    }
}

// ---------------- k_wqfin: finalize partials + sign quantize --------------
__global__ __launch_bounds__(256) void k_wqfin(
    const float* __restrict__ Wg, const float* __restrict__ Wu,
    const float* __restrict__ Wd, const float* __restrict__ sWg,
    const float* __restrict__ sWu, const float* __restrict__ sWd) {
    int m = blockIdx.y;
    int kind = m / NEXP, e = m % NEXP;
    const float* base =
        (kind == 0) ? ((e < 8) ? Wg + (size_t)e * NW : sWg)
      : (kind == 1) ? ((e < 8) ? Wu + (size_t)e * NW : sWu)
                    : ((e < 8) ? Wd + (size_t)e * NW : sWd);
    __shared__ double rs[RED_BLK], ra[RED_BLK];
    __shared__ float s_mean;
    int tid = threadIdx.x;
    if (tid < RED_BLK) {
        rs[tid] = g_part[(m * RED_BLK + tid) * 2 + 0];
        ra[tid] = g_part[(m * RED_BLK + tid) * 2 + 1];
    }
    __syncthreads();
    for (int o = RED_BLK / 2; o; o >>= 1) {
        if (tid < o) { rs[tid] += rs[tid + o]; ra[tid] += ra[tid + o]; }
        __syncthreads();
    }
    if (tid == 0) {
        s_mean = (float)(rs[0] / (double)NW);
        double sc = ra[0] / (double)NW;
        if (sc < 1e-8) sc = 1e-8;
        if (blockIdx.x == 0) g_wscale[m] = (float)sc;
    }
    __syncthreads();
    float mean = s_mean;
    int i = blockIdx.x * 256 + tid;
    const int N4 = NW / 4;
    if (i >= N4) return;
    float4 v = ((const float4*)base)[i];
    char4 q;
    q.x = (v.x > mean) ? 1 : ((v.x < mean) ? -1 : 0);
    q.y = (v.y > mean) ? 1 : ((v.y < mean) ? -1 : 0);
    q.z = (v.z > mean) ? 1 : ((v.z < mean) ? -1 : 0);
    q.w = (v.w > mean) ? 1 : ((v.w < mean) ? -1 : 0);
    ((char4*)&g_qw[kind][e][0])[i] = q;
}

// ---------------- input rmsnorm + act quant: warp per row ----------------
__global__ __launch_bounds__(256) void k_xq_all(const float* __restrict__ x,
                                                const float* __restrict__ ng,
                                                const float* __restrict__ nu,
                                                const float* __restrict__ sng,
                                                const float* __restrict__ snu) {
    int e = blockIdx.y;
    int wid = threadIdx.x >> 5, lane = threadIdx.x & 31;
    int r = blockIdx.x * 8 + wid;
    if (r >= g_cnt[e]) return;
    const float* nwg = (e < 8) ? ng + (size_t)e * HD : sng;
    const float* nwu = (e < 8) ? nu + (size_t)e * HD : snu;
    int t = g_lidx[e * TOK + r];
    const float4* xr4 = (const float4*)(x + (size_t)t * HD);
    const float4* ng4 = (const float4*)nwg;
    const float4* nu4 = (const float4*)nwu;

    float v[24], gw[24], uw[24];
    float ssum = 0.f;
#pragma unroll
    for (int i = 0; i < 6; i++) {
        float4 w = xr4[lane + i * 32];
        float4 a = ng4[lane + i * 32];
        float4 b = nu4[lane + i * 32];
        float c0 = clipf(w.x, -100.f, 100.f), c1 = clipf(w.y, -100.f, 100.f);
        float c2 = clipf(w.z, -100.f, 100.f), c3 = clipf(w.w, -100.f, 100.f);
        v[i*4+0] = c0; v[i*4+1] = c1; v[i*4+2] = c2; v[i*4+3] = c3;
        ssum += c0*c0 + c1*c1 + c2*c2 + c3*c3;
        gw[i*4+0] = a.x; gw[i*4+1] = a.y; gw[i*4+2] = a.z; gw[i*4+3] = a.w;
        uw[i*4+0] = b.x; uw[i*4+1] = b.y; uw[i*4+2] = b.z; uw[i*4+3] = b.w;
    }
#pragma unroll
    for (int o = 16; o; o >>= 1) ssum += __shfl_xor_sync(0xFFFFFFFFu, ssum, o);
    float var = fmaxf(ssum / (float)HD, 1e-5f);
    float rinv = 1.f / sqrtf(var + 1e-5f);

    float mg = 0.f, mu = 0.f;
#pragma unroll
    for (int i = 0; i < 24; i++) {
        float xh = clipf(v[i] * rinv, -10.f, 10.f);
        float vg = clipf(gw[i] * xh, -50.f, 50.f);
        float vu = clipf(uw[i] * xh, -50.f, 50.f);
        gw[i] = vg; uw[i] = vu;
        mg = fmaxf(mg, fabsf(vg));
        mu = fmaxf(mu, fabsf(vu));
    }
#pragma unroll
    for (int o = 16; o; o >>= 1) {
        mg = fmaxf(mg, __shfl_xor_sync(0xFFFFFFFFu, mg, o));
        mu = fmaxf(mu, __shfl_xor_sync(0xFFFFFFFFu, mu, o));
    }
    mg = fmaxf(mg, 1e-4f); mu = fmaxf(mu, 1e-4f);
    if (lane == 0) { g_ag[e * TOK + r] = mg / 127.f; g_au[e * TOK + r] = mu / 127.f; }
    float scg = 127.f / mg, scu = 127.f / mu;
    size_t rowoff = ((size_t)e * TOK + r) * HD;
    char4* og = (char4*)(g_xg + rowoff);
    char4* ou = (char4*)(g_xu + rowoff);
#pragma unroll
    for (int i = 0; i < 6; i++) {
        char4 qg, qu;
        int q;
        q = (int)rintf(gw[i*4+0] * scg); qg.x = (char)max(-128, min(127, q));
        q = (int)rintf(gw[i*4+1] * scg); qg.y = (char)max(-128, min(127, q));
        q = (int)rintf(gw[i*4+2] * scg); qg.z = (char)max(-128, min(127, q));
        q = (int)rintf(gw[i*4+3] * scg); qg.w = (char)max(-128, min(127, q));
        q = (int)rintf(uw[i*4+0] * scu); qu.x = (char)max(-128, min(127, q));
        q = (int)rintf(uw[i*4+1] * scu); qu.y = (char)max(-128, min(127, q));
        q = (int)rintf(uw[i*4+2] * scu); qu.z = (char)max(-128, min(127, q));
        q = (int)rintf(uw[i*4+3] * scu); qu.w = (char)max(-128, min(127, q));
        og[lane + i * 32] = qg;
        ou[lane + i * 32] = qu;
    }
}

// ---------------- hidden rmsnorm + quant: warp per row -------------------
__global__ __launch_bounds__(256) void k_hq_all(const float* __restrict__ nd,
                                                const float* __restrict__ snd) {
    int e = blockIdx.y;
    int wid = threadIdx.x >> 5, lane = threadIdx.x & 31;
    int r = blockIdx.x * 8 + wid;
    if (r >= g_cnt[e]) return;
    const float* nw = (e < 8) ? nd + (size_t)e * ID : snd;
    size_t rowoff = ((size_t)e * TOK + r) * ID;
    const float4* hr4 = (const float4*)(g_hidden + rowoff);
    const float4* nw4 = (const float4*)nw;

    float v[64];
    float ssum = 0.f;
#pragma unroll
    for (int i = 0; i < 16; i++) {
        float4 w = hr4[lane + i * 32];
        float c0 = clipf(w.x, -100.f, 100.f), c1 = clipf(w.y, -100.f, 100.f);
        float c2 = clipf(w.z, -100.f, 100.f), c3 = clipf(w.w, -100.f, 100.f);
        v[i*4+0] = c0; v[i*4+1] = c1; v[i*4+2] = c2; v[i*4+3] = c3;
        ssum += c0*c0 + c1*c1 + c2*c2 + c3*c3;
    }
#pragma unroll
    for (int o = 16; o; o >>= 1) ssum += __shfl_xor_sync(0xFFFFFFFFu, ssum, o);
    float var = fmaxf(ssum / (float)ID, 1e-5f);
    float rinv = 1.f / sqrtf(var + 1e-5f);

    float m = 0.f;
#pragma unroll
    for (int i = 0; i < 16; i++) {
        float4 a = nw4[lane + i * 32];
        float xh0 = clipf(v[i*4+0] * rinv, -10.f, 10.f);
        float xh1 = clipf(v[i*4+1] * rinv, -10.f, 10.f);
        float xh2 = clipf(v[i*4+2] * rinv, -10.f, 10.f);
        float xh3 = clipf(v[i*4+3] * rinv, -10.f, 10.f);
        v[i*4+0] = clipf(a.x * xh0, -50.f, 50.f);
        v[i*4+1] = clipf(a.y * xh1, -50.f, 50.f);
        v[i*4+2] = clipf(a.z * xh2, -50.f, 50.f);
        v[i*4+3] = clipf(a.w * xh3, -50.f, 50.f);
        m = fmaxf(m, fmaxf(fmaxf(fabsf(v[i*4+0]), fabsf(v[i*4+1])),
                           fmaxf(fabsf(v[i*4+2]), fabsf(v[i*4+3]))));
    }
#pragma unroll
    for (int o = 16; o; o >>= 1) m = fmaxf(m, __shfl_xor_sync(0xFFFFFFFFu, m, o));
    m = fmaxf(m, 1e-4f);
    if (lane == 0) g_ah[e * TOK + r] = m / 127.f;
    float sc = 127.f / m;
    char4* oq = (char4*)(g_hq + rowoff);
#pragma unroll
    for (int i = 0; i < 16; i++) {
        char4 q4;
        int q;
        q = (int)rintf(v[i*4+0] * sc); q4.x = (char)max(-128, min(127, q));
        q = (int)rintf(v[i*4+1] * sc); q4.y = (char)max(-128, min(127, q));
        q = (int)rintf(v[i*4+2] * sc); q4.z = (char)max(-128, min(127, q));
        q = (int)rintf(v[i*4+3] * sc); q4.w = (char)max(-128, min(127, q));
        oq[lane + i * 32] = q4;
    }
}

// ---------------- GEMM 1: gate+up, block-specialized mma|dp4a ------------
// grid (TOK/64, ID/64, NEXP), 256 threads, 64x64 tiles.
// path = (bx ^ by) & 1: 0 -> mma core, 1 -> dp4a core.
// Stage layout (per 20480B stage): Ag@0, Au@5120, Bg@10240, Bu@15360 (64x80 each).
#define GU_STG 20480
#define GU_SMEM (2 * GU_STG)
__global__ __launch_bounds__(256, 2) void k_gemm_gu() {
    int e = blockIdx.z;
    int n = g_cnt[e];
    int m0 = blockIdx.x * 64;
    if (m0 >= n) return;
    int n0 = blockIdx.y * 64;
    int is_mma = ((blockIdx.x ^ blockIdx.y) & 1) == 0;

    extern __shared__ __align__(16) uint8_t dsm[];
    uint32_t sb = smem_u32(dsm);

    const int4* Ag4 = (const int4*)(g_xg + (size_t)e * TOK * HD);
    const int4* Au4 = (const int4*)(g_xu + (size_t)e * TOK * HD);
    const int4* Bg4 = (const int4*)&g_qw[0][e][0];
    const int4* Bu4 = (const int4*)&g_qw[1][e][0];
    const int KI4 = HD / 16;  // 48

    int tid = threadIdx.x;
    int warp = tid >> 5, lane = tid & 31;
    int rw = warp & 3, cw = warp >> 2;          // mma: rows rw*16, cols cw*32
    int tx = tid & 15, ty = tid >> 4;           // dp4a: cols tx*4, rows ty*4

    int cg[4][4] = {}, cu[4][4] = {};           // mma acc
    int acg[4][4] = {}, acu[4][4] = {};         // dp4a acc

#define GU_ISSUE(kb_) do {                                                    \
        uint32_t b_ = sb + ((kb_) & 1) * GU_STG;                              \
        for (int i = tid; i < 1024; i += 256) {                               \
            int tt = i >> 8, rem = i & 255, row_ = rem >> 2, seg_ = rem & 3;  \
            uint32_t d_ = b_ + tt * 5120 + row_ * 80 + seg_ * 16;             \
            const int4* src;                                                  \
            if (tt == 0)                                                      \
                src = Ag4 + (size_t)min(m0 + row_, n - 1) * KI4 + (kb_) * 4 + seg_; \
            else if (tt == 1)                                                 \
                src = Au4 + (size_t)min(m0 + row_, n - 1) * KI4 + (kb_) * 4 + seg_; \
            else if (tt == 2)                                                 \
                src = Bg4 + (size_t)(n0 + row_) * KI4 + (kb_) * 4 + seg_;     \
            else                                                              \
                src = Bu4 + (size_t)(n0 + row_) * KI4 + (kb_) * 4 + seg_;     \
            cpa16(d_, src);                                                   \
        }                                                                     \
    } while (0)

    GU_ISSUE(0); CP_COMMIT();
    GU_ISSUE(1); CP_COMMIT();

    const int KB = HD / 64;  // 12
    for (int kb = 0; kb < KB; kb++) {
        CP_WAIT_1();
        __syncthreads();
        const uint8_t* st = dsm + (kb & 1) * GU_STG;
        if (is_mma) {
#pragma unroll
            for (int ks = 0; ks < 2; ks++) {
                int bg[4][2], bu[4][2];
#pragma unroll
                for (int nt = 0; nt < 4; nt++) {
                    uint32_t bo = (uint32_t)(cw * 32 + nt * 8) * 80 + ks * 32;
                    load_b_frag(bg[nt], st + 10240 + bo, lane);
                    load_b_frag(bu[nt], st + 15360 + bo, lane);
                }
                int ag[4], au[4];
                uint32_t ao = (uint32_t)(rw * 16) * 80 + ks * 32;
                load_a_frag(ag, st + ao, lane);
                load_a_frag(au, st + 5120 + ao, lane);
#pragma unroll
                for (int nt = 0; nt < 4; nt++) {
                    mma_s8(cg[nt], ag, bg[nt]);
                    mma_s8(cu[nt], au, bu[nt]);
                }
            }
        } else {
#pragma unroll
            for (int seg = 0; seg < 4; seg++) {
                int4 a_g[4], a_u[4], b_g[4], b_u[4];
#pragma unroll
                for (int i = 0; i < 4; i++) {
                    uint32_t ao = (uint32_t)(ty * 4 + i) * 80 + seg * 16;
                    a_g[i] = *(const int4*)(st + ao);
                    a_u[i] = *(const int4*)(st + 5120 + ao);
                }
#pragma unroll
                for (int j = 0; j < 4; j++) {
                    uint32_t bo = (uint32_t)(tx * 4 + j) * 80 + seg * 16;
                    b_g[j] = *(const int4*)(st + 10240 + bo);
                    b_u[j] = *(const int4*)(st + 15360 + bo);
                }
#pragma unroll
                for (int i = 0; i < 4; i++)
#pragma unroll
                    for (int j = 0; j < 4; j++) {
                        acg[i][j] = dp4(a_g[i], b_g[j], acg[i][j]);
                        acu[i][j] = dp4(a_u[i], b_u[j], acu[i][j]);
                    }
            }
        }
        __syncthreads();
        if (kb + 2 < KB) GU_ISSUE(kb + 2);
        CP_COMMIT();
    }
#undef GU_ISSUE

    float wsg = g_wscale[0 * NEXP + e];
    float wsu = g_wscale[1 * NEXP + e];
    float* H = g_hidden + (size_t)e * TOK * ID;
    if (is_mma) {
#pragma unroll
        for (int half = 0; half < 2; half++) {
            int r = m0 + rw * 16 + half * 8 + (lane >> 2);
            if (r >= n) continue;
            float sg = g_ag[e * TOK + r] * wsg;
            float su = g_au[e * TOK + r] * wsu;
            float* Hr = H + (size_t)r * ID;
#pragma unroll
            for (int nt = 0; nt < 4; nt++) {
                int c = n0 + cw * 32 + nt * 8 + (lane & 3) * 2;
                float2 o;
                float gg0 = clipf((float)cg[nt][half*2+0] * sg, -20.f, 20.f);
                float gg1 = clipf((float)cg[nt][half*2+1] * sg, -20.f, 20.f);
                float uu0 = (float)cu[nt][half*2+0] * su;
                float uu1 = (float)cu[nt][half*2+1] * su;
                o.x = clipf(gg0 * fast_sigmoid(gg0) * uu0, -1000.f, 1000.f);
                o.y = clipf(gg1 * fast_sigmoid(gg1) * uu1, -1000.f, 1000.f);
                *(float2*)(Hr + c) = o;
            }
        }
    } else {
#pragma unroll
        for (int i = 0; i < 4; i++) {
            int r = m0 + ty * 4 + i;
            if (r >= n) continue;
            float sg = g_ag[e * TOK + r] * wsg;
            float su = g_au[e * TOK + r] * wsu;
            float* Hr = H + (size_t)r * ID;
            float4 o;
            float* op = &o.x;
#pragma unroll
            for (int j = 0; j < 4; j++) {
                float gg = clipf((float)acg[i][j] * sg, -20.f, 20.f);
                float uu = (float)acu[i][j] * su;
                op[j] = clipf(gg * fast_sigmoid(gg) * uu, -1000.f, 1000.f);
            }
            *(float4*)(Hr + n0 + tx * 4) = o;
        }
    }
}

// ---------------- GEMM 2: down, block-specialized mma|dp4a, scatter ------
// grid (TOK/64, HD/64, NEXP), 256 threads, 64x64 tiles.
// Stage (10240B): A@0, B@5120.
#define D_STG 10240
__global__ __launch_bounds__(256, 3) void k_gemm_d(float* __restrict__ out) {
    int e = blockIdx.z;
    int n = g_cnt[e];
    int m0 = blockIdx.x * 64;
    if (m0 >= n) return;
    int n0 = blockIdx.y * 64;
    int is_mma = ((blockIdx.x ^ blockIdx.y) & 1) == 0;

    __shared__ __align__(16) uint8_t dsm[2 * D_STG];
    uint32_t sb = smem_u32(dsm);

    const int4* A4 = (const int4*)(g_hq + (size_t)e * TOK * ID);
    const int4* B4 = (const int4*)&g_qw[2][e][0];
    const int KI4 = ID / 16;  // 128

    int tid = threadIdx.x;
    int warp = tid >> 5, lane = tid & 31;
    int rw = warp & 3, cw = warp >> 2;
    int tx = tid & 15, ty = tid >> 4;

    int acc[4][4] = {};   // mma
    int acd[4][4] = {};   // dp4a

#define D_ISSUE(kb_) do {                                                     \
        uint32_t b_ = sb + ((kb_) & 1) * D_STG;                               \
        for (int i = tid; i < 512; i += 256) {                                \
            int tt = i >> 8, rem = i & 255, row_ = rem >> 2, seg_ = rem & 3;  \
            uint32_t d_ = b_ + tt * 5120 + row_ * 80 + seg_ * 16;             \
            const int4* src = (tt == 0)                                       \
                ? A4 + (size_t)min(m0 + row_, n - 1) * KI4 + (kb_) * 4 + seg_ \
                : B4 + (size_t)(n0 + row_) * KI4 + (kb_) * 4 + seg_;          \
            cpa16(d_, src);                                                   \
        }                                                                     \
    } while (0)

    D_ISSUE(0); CP_COMMIT();
    D_ISSUE(1); CP_COMMIT();

    const int KB = ID / 64;  // 32
    for (int kb = 0; kb < KB; kb++) {
        CP_WAIT_1();
        __syncthreads();
        const uint8_t* st = dsm + (kb & 1) * D_STG;
        if (is_mma) {
#pragma unroll
            for (int ks = 0; ks < 2; ks++) {
                int b[4][2];
#pragma unroll
                for (int nt = 0; nt < 4; nt++)
                    load_b_frag(b[nt], st + 5120 +
                                (uint32_t)(cw * 32 + nt * 8) * 80 + ks * 32, lane);
                int a[4];
                load_a_frag(a, st + (uint32_t)(rw * 16) * 80 + ks * 32, lane);
#pragma unroll
                for (int nt = 0; nt < 4; nt++)
                    mma_s8(acc[nt], a, b[nt]);
            }
        } else {
#pragma unroll
            for (int seg = 0; seg < 4; seg++) {
                int4 av[4], bv[4];
#pragma unroll
                for (int i = 0; i < 4; i++)
                    av[i] = *(const int4*)(st + (uint32_t)(ty * 4 + i) * 80 + seg * 16);
#pragma unroll
                for (int j = 0; j < 4; j++)
                    bv[j] = *(const int4*)(st + 5120 +
                                           (uint32_t)(tx * 4 + j) * 80 + seg * 16);
#pragma unroll
                for (int i = 0; i < 4; i++)
#pragma unroll
                    for (int j = 0; j < 4; j++)
                        acd[i][j] = dp4(av[i], bv[j], acd[i][j]);
            }
        }
        __syncthreads();
        if (kb + 2 < KB) D_ISSUE(kb + 2);
        CP_COMMIT();
    }
#undef D_ISSUE

    float wsd = g_wscale[2 * NEXP + e];
    if (is_mma) {
#pragma unroll
        for (int half = 0; half < 2; half++) {
            int r = m0 + rw * 16 + half * 8 + (lane >> 2);
            if (r >= n) continue;
            float s = g_ah[e * TOK + r] * wsd;
            int t = g_lidx[e * TOK + r];
            float lw = g_lw[e * TOK + r];
            float* outr = out + (size_t)t * HD;
#pragma unroll
            for (int nt = 0; nt < 4; nt++) {
                int c = n0 + cw * 32 + nt * 8 + (lane & 3) * 2;
                atomicAdd(outr + c,     lw * ((float)acc[nt][half*2+0] * s));
                atomicAdd(outr + c + 1, lw * ((float)acc[nt][half*2+1] * s));
            }
        }
    } else {
#pragma unroll
        for (int i = 0; i < 4; i++) {
            int r = m0 + ty * 4 + i;
            if (r >= n) continue;
            float s = g_ah[e * TOK + r] * wsd;
            int t = g_lidx[e * TOK + r];
            float lw = g_lw[e * TOK + r];
            float* outr = out + (size_t)t * HD + n0 + tx * 4;
#pragma unroll
            for (int j = 0; j < 4; j++)
                atomicAdd(outr + j, lw * ((float)acd[i][j] * s));
        }
    }
}

__global__ void k_clip(float* out, int n) {
    int i = blockIdx.x * blockDim.x + threadIdx.x;
    if (i < n) out[i] = clipf(out[i], -10000.f, 10000.f);
    if (i < NEXP) g_cnt[i] = 0;    // re-arm expert counters for next replay
}

// ---------------- launcher ----------------
extern "C" void kernel_launch(void* const* d_in, const int* in_sizes, int n_in,
                              void* d_out, int out_size) {
    const float* x   = (const float*)d_in[0];
    const float* rw  = (const float*)d_in[1];
    const float* rb  = (const float*)d_in[2];
    const float* Wg  = (const float*)d_in[3];
    const float* Wu  = (const float*)d_in[4];
    const float* Wd  = (const float*)d_in[5];
    const float* ng  = (const float*)d_in[6];
    const float* nu  = (const float*)d_in[7];
    const float* nd  = (const float*)d_in[8];
    const float* sWg = (const float*)d_in[9];
    const float* sWu = (const float*)d_in[10];
    const float* sWd = (const float*)d_in[11];
    const float* sng = (const float*)d_in[12];
    const float* snu = (const float*)d_in[13];
    const float* snd = (const float*)d_in[14];
    float* out = (float*)d_out;

    float* logits_dst;
    if (out_size >= TOK * HD + TOK * 8) {
        logits_dst = out + (size_t)TOK * HD;
    } else {
        void* p = nullptr;
        cudaGetSymbolAddress(&p, g_logits_scratch);
        logits_dst = (float*)p;
    }

    cudaFuncSetAttribute(k_gemm_gu,
                         cudaFuncAttributeMaxDynamicSharedMemorySize, GU_SMEM);

    // gu GEMM at launch slot #4 (the slot ncu captures)
    k_pre<<<RED_BLK * NMAT + TOK, 256>>>(x, rw, rb, logits_dst, out,
                                         Wg, Wu, Wd, sWg, sWu, sWd);       // 1
    k_wqfin<<<dim3(NW / 4 / 256, NMAT), 256>>>(Wg, Wu, Wd, sWg, sWu, sWd); // 2
    k_xq_all<<<dim3(TOK / 8, NEXP), 256>>>(x, ng, nu, sng, snu);           // 3
    k_gemm_gu<<<dim3(TOK / 64, ID / 64, NEXP), 256, GU_SMEM>>>();          // 4 <- ncu
    k_hq_all<<<dim3(TOK / 8, NEXP), 256>>>(nd, snd);                       // 5
    k_gemm_d<<<dim3(TOK / 64, HD / 64, NEXP), 256>>>(out);                 // 6
    k_clip<<<(TOK * HD + 255) / 256, 256>>>(out, TOK * HD);                // 7
}

// round 16
// speedup vs baseline: 1.4431x; 1.4431x over previous
#include <cuda_runtime.h>
#include <math.h>
#include <stdint.h>

// BitNet MoE layer, GB300.  R16 (final form): R10's proven mma.sync GEMMs
// VERBATIM (128 thr, 128x64 tiles, scalar LDS frags, 2-stage cp.async —
// benched 1847us, tensor pipe ~93% = legacy-IMMA ceiling; tcgen05 is
// compiler-gated off and dp4a hybrids are smem-crossbar-capped per R15's
// L1=74.5% profile) + the launch fusions proven across R11-R15:
// k_pre (wred+router+zero) and k_wqfin (finalize+sign-quant).

#define TOK  8192
#define HD   768
#define ID   2048
#define NEXP 9
#define NMAT 27
#define NW   (ID*HD)
#define RED_BLK 64

// ---------------- scratch (device globals; allocation-free) ----------------
__device__ __align__(16) int8_t g_qw[3][NEXP][NW];            // {-1,0,1}
__device__ double g_part[NMAT * RED_BLK * 2];
__device__ float  g_wscale[NMAT];
__device__ float  g_logits_scratch[TOK * 8];
__device__ int    g_cnt[NEXP];                                 // re-zeroed by k_clip
__device__ int    g_lidx[NEXP * TOK];
__device__ float  g_lw[NEXP * TOK];
__device__ __align__(16) int8_t g_xg[(size_t)NEXP * TOK * HD];
__device__ __align__(16) int8_t g_xu[(size_t)NEXP * TOK * HD];
__device__ float  g_ag[NEXP * TOK], g_au[NEXP * TOK], g_ah[NEXP * TOK];
__device__ __align__(16) float  g_hidden[(size_t)NEXP * TOK * ID];
__device__ __align__(16) int8_t g_hq[(size_t)NEXP * TOK * ID];

__device__ __forceinline__ float clipf(float v, float lo, float hi) {
    return fminf(fmaxf(v, lo), hi);
}

__device__ __forceinline__ float fast_sigmoid(float g) {
    float ax = fabsf(g);
    float z  = -1.4426950408889634f * ax;
    float nf = rintf(z);
    float f  = z - nf;
    float p  = 1.5403530e-4f;
    p = fmaf(p, f, 1.33335581e-3f);
    p = fmaf(p, f, 9.61812911e-3f);
    p = fmaf(p, f, 5.55041087e-2f);
    p = fmaf(p, f, 2.40226507e-1f);
    p = fmaf(p, f, 6.93147181e-1f);
    p = fmaf(p, f, 1.0f);
    float s = __int_as_float(((int)nf + 127) << 23);
    float t = p * s;
    float d = 1.0f + t;
    float r = __int_as_float(0x7EF311C3 - __float_as_int(d));
    r = r * (2.0f - d * r);
    r = r * (2.0f - d * r);
    r = r * (2.0f - d * r);
    return (g >= 0.f) ? r : 1.0f - r;
}

__device__ __forceinline__ uint32_t smem_u32(const void* p) {
    uint32_t a;
    asm("{ .reg .u64 t; cvta.to.shared.u64 t, %1; cvt.u32.u64 %0, t; }"
        : "=r"(a) : "l"(p));
    return a;
}
__device__ __forceinline__ void cpa16(uint32_t dst, const void* src) {
    asm volatile("cp.async.cg.shared.global [%0], [%1], 16;"
                 :: "r"(dst), "l"(src) : "memory");
}
#define CP_COMMIT() asm volatile("cp.async.commit_group;" ::: "memory")
#define CP_WAIT1()  asm volatile("cp.async.wait_group 1;" ::: "memory")

__device__ __forceinline__ void mma_s8(int* c, const int* a, const int* b) {
    asm volatile(
        "mma.sync.aligned.m16n8k32.row.col.s32.s8.s8.s32 "
        "{%0,%1,%2,%3}, {%4,%5,%6,%7}, {%8,%9}, {%0,%1,%2,%3};"
        : "+r"(c[0]), "+r"(c[1]), "+r"(c[2]), "+r"(c[3])
        : "r"(a[0]), "r"(a[1]), "r"(a[2]), "r"(a[3]), "r"(b[0]), "r"(b[1]));
}
// R10-proven scalar-LDS fragment loads (stride 80 B, conflict-free)
__device__ __forceinline__ void load_a_frag(int* a, const int8_t* smem_row0,
                                            int lane) {
    const int8_t* p = smem_row0 + (lane >> 2) * 80 + (lane & 3) * 4;
    a[0] = *(const int*)(p);
    a[1] = *(const int*)(p + 8 * 80);
    a[2] = *(const int*)(p + 16);
    a[3] = *(const int*)(p + 8 * 80 + 16);
}
__device__ __forceinline__ void load_b_frag(int* b, const int8_t* smem_row0,
                                            int lane) {
    const int8_t* p = smem_row0 + (lane >> 2) * 80 + (lane & 3) * 4;
    b[0] = *(const int*)(p);
    b[1] = *(const int*)(p + 16);
}

// ---------------- k_pre: weight reductions + router/top2 (fused) ----------
__global__ __launch_bounds__(256) void k_pre(
    const float* __restrict__ x,  const float* __restrict__ rw,
    const float* __restrict__ rb, float* __restrict__ logits_out,
    float* __restrict__ out,
    const float* __restrict__ Wg, const float* __restrict__ Wu,
    const float* __restrict__ Wd, const float* __restrict__ sWg,
    const float* __restrict__ sWu, const float* __restrict__ sWd) {
    int b = blockIdx.x, tid = threadIdx.x;
    if (b < RED_BLK * NMAT) {
        int m = b / RED_BLK, bx = b % RED_BLK;
        int kind = m / NEXP, e = m % NEXP;
        const float* base =
            (kind == 0) ? ((e < 8) ? Wg + (size_t)e * NW : sWg)
          : (kind == 1) ? ((e < 8) ? Wu + (size_t)e * NW : sWu)
                        : ((e < 8) ? Wd + (size_t)e * NW : sWd);
        const float4* w4 = (const float4*)base;
        const int N4 = NW / 4;
        float s = 0.f, a = 0.f;
        for (int i = bx * 256 + tid; i < N4; i += RED_BLK * 256) {
            float4 v = w4[i];
            s += (v.x + v.y) + (v.z + v.w);
            a += (fabsf(v.x) + fabsf(v.y)) + (fabsf(v.z) + fabsf(v.w));
        }
        __shared__ double ss[256], sa[256];
        ss[tid] = (double)s; sa[tid] = (double)a;
        __syncthreads();
        for (int o = 128; o; o >>= 1) {
            if (tid < o) { ss[tid] += ss[tid + o]; sa[tid] += sa[tid + o]; }
            __syncthreads();
        }
        if (tid == 0) {
            g_part[(m * RED_BLK + bx) * 2 + 0] = ss[0];
            g_part[(m * RED_BLK + bx) * 2 + 1] = sa[0];
        }
        return;
    }
    // ---- router part ----
    int t = b - RED_BLK * NMAT;
    for (int j = tid; j < HD; j += 256) out[(size_t)t * HD + j] = 0.f;
    const float* xr = x + (size_t)t * HD;
    float acc[8];
#pragma unroll
    for (int e = 0; e < 8; e++) acc[e] = 0.f;
    for (int h = tid; h < HD; h += 256) {
        float xv = xr[h];
#pragma unroll
        for (int e = 0; e < 8; e++) acc[e] += xv * rw[e * HD + h];
    }
    __shared__ float s2[8][256];
#pragma unroll
    for (int e = 0; e < 8; e++) s2[e][tid] = acc[e];
    __syncthreads();
    for (int o = 128; o; o >>= 1) {
        if (tid < o) {
#pragma unroll
            for (int e = 0; e < 8; e++) s2[e][tid] += s2[e][tid + o];
        }
        __syncthreads();
    }
    if (tid == 0) {
        float l[8], p[8];
        float mx = -1e30f;
#pragma unroll
        for (int e = 0; e < 8; e++) {
            l[e] = s2[e][0] + rb[e];
            logits_out[t * 8 + e] = l[e];
            mx = fmaxf(mx, l[e]);
        }
        float ps = 0.f;
#pragma unroll
        for (int e = 0; e < 8; e++) { p[e] = expf(l[e] - mx); ps += p[e]; }
#pragma unroll
        for (int e = 0; e < 8; e++) p[e] /= ps;
        int i1 = 0;
#pragma unroll
        for (int e = 1; e < 8; e++) if (p[e] > p[i1]) i1 = e;
        int i2 = -1;
#pragma unroll
        for (int e = 0; e < 8; e++) {
            if (e == i1) continue;
            if (i2 < 0 || p[e] > p[i2]) i2 = e;
        }
        float den = p[i1] + p[i2] + 1e-8f;
        int p1 = atomicAdd(&g_cnt[i1], 1);
        g_lidx[i1 * TOK + p1] = t;
        g_lw[i1 * TOK + p1] = p[i1] / den;
        int p2 = atomicAdd(&g_cnt[i2], 1);
        g_lidx[i2 * TOK + p2] = t;
        g_lw[i2 * TOK + p2] = p[i2] / den;
        g_lidx[8 * TOK + t] = t;
        g_lw[8 * TOK + t] = 1.f;
        if (t == 0) g_cnt[8] = TOK;
    }
}

// ---------------- k_wqfin: finalize partials + sign quantize (fused) ------
__global__ __launch_bounds__(256) void k_wqfin(
    const float* __restrict__ Wg, const float* __restrict__ Wu,
    const float* __restrict__ Wd, const float* __restrict__ sWg,
    const float* __restrict__ sWu, const float* __restrict__ sWd) {
    int m = blockIdx.y;
    int kind = m / NEXP, e = m % NEXP;
    const float* base =
        (kind == 0) ? ((e < 8) ? Wg + (size_t)e * NW : sWg)
      : (kind == 1) ? ((e < 8) ? Wu + (size_t)e * NW : sWu)
                    : ((e < 8) ? Wd + (size_t)e * NW : sWd);
    __shared__ double rs[RED_BLK], ra[RED_BLK];
    __shared__ float s_mean;
    int tid = threadIdx.x;
    if (tid < RED_BLK) {
        rs[tid] = g_part[(m * RED_BLK + tid) * 2 + 0];
        ra[tid] = g_part[(m * RED_BLK + tid) * 2 + 1];
    }
    __syncthreads();
    for (int o = RED_BLK / 2; o; o >>= 1) {
        if (tid < o) { rs[tid] += rs[tid + o]; ra[tid] += ra[tid + o]; }
        __syncthreads();
    }
    if (tid == 0) {
        s_mean = (float)(rs[0] / (double)NW);
        double sc = ra[0] / (double)NW;
        if (sc < 1e-8) sc = 1e-8;
        if (blockIdx.x == 0) g_wscale[m] = (float)sc;
    }
    __syncthreads();
    float mean = s_mean;
    int i = blockIdx.x * 256 + tid;
    const int N4 = NW / 4;
    if (i >= N4) return;
    float4 v = ((const float4*)base)[i];
    char4 q;
    q.x = (v.x > mean) ? 1 : ((v.x < mean) ? -1 : 0);
    q.y = (v.y > mean) ? 1 : ((v.y < mean) ? -1 : 0);
    q.z = (v.z > mean) ? 1 : ((v.z < mean) ? -1 : 0);
    q.w = (v.w > mean) ? 1 : ((v.w < mean) ? -1 : 0);
    ((char4*)&g_qw[kind][e][0])[i] = q;
}

// ---------------- input rmsnorm + act quant: warp per row (R10) ----------
__global__ __launch_bounds__(256) void k_xq_all(const float* __restrict__ x,
                                                const float* __restrict__ ng,
                                                const float* __restrict__ nu,
                                                const float* __restrict__ sng,
                                                const float* __restrict__ snu) {
    int e = blockIdx.y;
    int wid = threadIdx.x >> 5, lane = threadIdx.x & 31;
    int r = blockIdx.x * 8 + wid;
    if (r >= g_cnt[e]) return;
    const float* nwg = (e < 8) ? ng + (size_t)e * HD : sng;
    const float* nwu = (e < 8) ? nu + (size_t)e * HD : snu;
    int t = g_lidx[e * TOK + r];
    const float4* xr4 = (const float4*)(x + (size_t)t * HD);
    const float4* ng4 = (const float4*)nwg;
    const float4* nu4 = (const float4*)nwu;

    float v[24], gw[24], uw[24];
    float ssum = 0.f;
#pragma unroll
    for (int i = 0; i < 6; i++) {
        float4 w = xr4[lane + i * 32];
        float4 a = ng4[lane + i * 32];
        float4 b = nu4[lane + i * 32];
        float c0 = clipf(w.x, -100.f, 100.f), c1 = clipf(w.y, -100.f, 100.f);
        float c2 = clipf(w.z, -100.f, 100.f), c3 = clipf(w.w, -100.f, 100.f);
        v[i*4+0] = c0; v[i*4+1] = c1; v[i*4+2] = c2; v[i*4+3] = c3;
        ssum += c0*c0 + c1*c1 + c2*c2 + c3*c3;
        gw[i*4+0] = a.x; gw[i*4+1] = a.y; gw[i*4+2] = a.z; gw[i*4+3] = a.w;
        uw[i*4+0] = b.x; uw[i*4+1] = b.y; uw[i*4+2] = b.z; uw[i*4+3] = b.w;
    }
#pragma unroll
    for (int o = 16; o; o >>= 1) ssum += __shfl_xor_sync(0xFFFFFFFFu, ssum, o);
    float var = fmaxf(ssum / (float)HD, 1e-5f);
    float rinv = 1.f / sqrtf(var + 1e-5f);

    float mg = 0.f, mu = 0.f;
#pragma unroll
    for (int i = 0; i < 24; i++) {
        float xh = clipf(v[i] * rinv, -10.f, 10.f);
        float vg = clipf(gw[i] * xh, -50.f, 50.f);
        float vu = clipf(uw[i] * xh, -50.f, 50.f);
        gw[i] = vg; uw[i] = vu;
        mg = fmaxf(mg, fabsf(vg));
        mu = fmaxf(mu, fabsf(vu));
    }
#pragma unroll
    for (int o = 16; o; o >>= 1) {
        mg = fmaxf(mg, __shfl_xor_sync(0xFFFFFFFFu, mg, o));
        mu = fmaxf(mu, __shfl_xor_sync(0xFFFFFFFFu, mu, o));
    }
    mg = fmaxf(mg, 1e-4f); mu = fmaxf(mu, 1e-4f);
    if (lane == 0) { g_ag[e * TOK + r] = mg / 127.f; g_au[e * TOK + r] = mu / 127.f; }
    float scg = 127.f / mg, scu = 127.f / mu;
    size_t rowoff = ((size_t)e * TOK + r) * HD;
    char4* og = (char4*)(g_xg + rowoff);
    char4* ou = (char4*)(g_xu + rowoff);
#pragma unroll
    for (int i = 0; i < 6; i++) {
        char4 qg, qu;
        int q;
        q = (int)rintf(gw[i*4+0] * scg); qg.x = (char)max(-128, min(127, q));
        q = (int)rintf(gw[i*4+1] * scg); qg.y = (char)max(-128, min(127, q));
        q = (int)rintf(gw[i*4+2] * scg); qg.z = (char)max(-128, min(127, q));
        q = (int)rintf(gw[i*4+3] * scg); qg.w = (char)max(-128, min(127, q));
        q = (int)rintf(uw[i*4+0] * scu); qu.x = (char)max(-128, min(127, q));
        q = (int)rintf(uw[i*4+1] * scu); qu.y = (char)max(-128, min(127, q));
        q = (int)rintf(uw[i*4+2] * scu); qu.z = (char)max(-128, min(127, q));
        q = (int)rintf(uw[i*4+3] * scu); qu.w = (char)max(-128, min(127, q));
        og[lane + i * 32] = qg;
        ou[lane + i * 32] = qu;
    }
}

// ---------------- hidden rmsnorm + quant: warp per row (R10) -------------
__global__ __launch_bounds__(256) void k_hq_all(const float* __restrict__ nd,
                                                const float* __restrict__ snd) {
    int e = blockIdx.y;
    int wid = threadIdx.x >> 5, lane = threadIdx.x & 31;
    int r = blockIdx.x * 8 + wid;
    if (r >= g_cnt[e]) return;
    const float* nw = (e < 8) ? nd + (size_t)e * ID : snd;
    size_t rowoff = ((size_t)e * TOK + r) * ID;
    const float4* hr4 = (const float4*)(g_hidden + rowoff);
    const float4* nw4 = (const float4*)nw;

    float v[64];
    float ssum = 0.f;
#pragma unroll
    for (int i = 0; i < 16; i++) {
        float4 w = hr4[lane + i * 32];
        float c0 = clipf(w.x, -100.f, 100.f), c1 = clipf(w.y, -100.f, 100.f);
        float c2 = clipf(w.z, -100.f, 100.f), c3 = clipf(w.w, -100.f, 100.f);
        v[i*4+0] = c0; v[i*4+1] = c1; v[i*4+2] = c2; v[i*4+3] = c3;
        ssum += c0*c0 + c1*c1 + c2*c2 + c3*c3;
    }
#pragma unroll
    for (int o = 16; o; o >>= 1) ssum += __shfl_xor_sync(0xFFFFFFFFu, ssum, o);
    float var = fmaxf(ssum / (float)ID, 1e-5f);
    float rinv = 1.f / sqrtf(var + 1e-5f);

    float m = 0.f;
#pragma unroll
    for (int i = 0; i < 16; i++) {
        float4 a = nw4[lane + i * 32];
        float xh0 = clipf(v[i*4+0] * rinv, -10.f, 10.f);
        float xh1 = clipf(v[i*4+1] * rinv, -10.f, 10.f);
        float xh2 = clipf(v[i*4+2] * rinv, -10.f, 10.f);
        float xh3 = clipf(v[i*4+3] * rinv, -10.f, 10.f);
        v[i*4+0] = clipf(a.x * xh0, -50.f, 50.f);
        v[i*4+1] = clipf(a.y * xh1, -50.f, 50.f);
        v[i*4+2] = clipf(a.z * xh2, -50.f, 50.f);
        v[i*4+3] = clipf(a.w * xh3, -50.f, 50.f);
        m = fmaxf(m, fmaxf(fmaxf(fabsf(v[i*4+0]), fabsf(v[i*4+1])),
                           fmaxf(fabsf(v[i*4+2]), fabsf(v[i*4+3]))));
    }
#pragma unroll
    for (int o = 16; o; o >>= 1) m = fmaxf(m, __shfl_xor_sync(0xFFFFFFFFu, m, o));
    m = fmaxf(m, 1e-4f);
    if (lane == 0) g_ah[e * TOK + r] = m / 127.f;
    float sc = 127.f / m;
    char4* oq = (char4*)(g_hq + rowoff);
#pragma unroll
    for (int i = 0; i < 16; i++) {
        char4 q4;
        int q;
        q = (int)rintf(v[i*4+0] * sc); q4.x = (char)max(-128, min(127, q));
        q = (int)rintf(v[i*4+1] * sc); q4.y = (char)max(-128, min(127, q));
        q = (int)rintf(v[i*4+2] * sc); q4.z = (char)max(-128, min(127, q));
        q = (int)rintf(v[i*4+3] * sc); q4.w = (char)max(-128, min(127, q));
        oq[lane + i * 32] = q4;
    }
}

// ---------------- GEMM 1: gate+up, R10 VERBATIM (1847us benched) ---------
// grid (TOK/128, ID/64, NEXP), 128 threads; dyn smem 2 stages x 30720 B.
#define GU_STG 30720
#define GU_SMEM (2 * GU_STG)
__global__ __launch_bounds__(128) void k_gemm_gu() {
    int e = blockIdx.z;
    int n = g_cnt[e];
    int m0 = blockIdx.x * 128;
    if (m0 >= n) return;
    int n0 = blockIdx.y * 64;

    extern __shared__ __align__(16) uint8_t dsm[];
    uint32_t sb = smem_u32(dsm);

    const int4* Ag4 = (const int4*)(g_xg + (size_t)e * TOK * HD);
    const int4* Au4 = (const int4*)(g_xu + (size_t)e * TOK * HD);
    const int4* Bg4 = (const int4*)&g_qw[0][e][0];
    const int4* Bu4 = (const int4*)&g_qw[1][e][0];
    const int KI4 = HD / 16;  // 48

    int tid = threadIdx.x;
    int warp = tid >> 5, lane = tid & 31;
    int wm = (warp >> 1) * 64;
    int wn = (warp & 1) * 32;

    int cg[4][4][4] = {};
    int cu[4][4][4] = {};

#define GU_ISSUE(kb_) do {                                                    \
        int st_ = (kb_) & 1; uint32_t b_ = sb + st_ * GU_STG;                 \
        for (int i = tid; i < 512; i += 128) {                                \
            int row_ = i >> 2, seg_ = i & 3;                                  \
            int grc_ = min(m0 + row_, n - 1);                                 \
            uint32_t d_ = b_ + row_ * 80 + seg_ * 16;                         \
            cpa16(d_,         Ag4 + (size_t)grc_ * KI4 + (kb_) * 4 + seg_);  \
            cpa16(d_ + 10240, Au4 + (size_t)grc_ * KI4 + (kb_) * 4 + seg_);  \
        }                                                                     \
        for (int i = tid; i < 256; i += 128) {                                \
            int row_ = i >> 2, seg_ = i & 3;                                  \
            int br_ = n0 + row_;                                              \
            uint32_t d_ = b_ + 20480 + row_ * 80 + seg_ * 16;                 \
            cpa16(d_,        Bg4 + (size_t)br_ * KI4 + (kb_) * 4 + seg_);    \
            cpa16(d_ + 5120, Bu4 + (size_t)br_ * KI4 + (kb_) * 4 + seg_);    \
        }                                                                     \
    } while (0)

    GU_ISSUE(0); CP_COMMIT();
    GU_ISSUE(1); CP_COMMIT();

    const int KB = HD / 64;  // 12
    for (int kb = 0; kb < KB; kb++) {
        CP_WAIT1();
        __syncthreads();
        int st = kb & 1;
        const int8_t* pAg = (const int8_t*)(dsm + st * GU_STG);
        const int8_t* pAu = pAg + 10240;
        const int8_t* pBg = pAg + 20480;
        const int8_t* pBu = pAg + 25600;
#pragma unroll
        for (int ks = 0; ks < 2; ks++) {
            int bg[4][2], bu[4][2];
#pragma unroll
            for (int nt = 0; nt < 4; nt++) {
                load_b_frag(bg[nt], pBg + (wn + nt * 8) * 80 + ks * 32, lane);
                load_b_frag(bu[nt], pBu + (wn + nt * 8) * 80 + ks * 32, lane);
            }
#pragma unroll
            for (int mt = 0; mt < 4; mt++) {
                int ag[4], au[4];
                load_a_frag(ag, pAg + (wm + mt * 16) * 80 + ks * 32, lane);
                load_a_frag(au, pAu + (wm + mt * 16) * 80 + ks * 32, lane);
#pragma unroll
                for (int nt = 0; nt < 4; nt++) {
                    mma_s8(cg[mt][nt], ag, bg[nt]);
                    mma_s8(cu[mt][nt], au, bu[nt]);
                }
            }
        }
        __syncthreads();
        if (kb + 2 < KB) GU_ISSUE(kb + 2);
        CP_COMMIT();
    }
#undef GU_ISSUE

    float wsg = g_wscale[0 * NEXP + e];
    float wsu = g_wscale[1 * NEXP + e];
    float* H = g_hidden + (size_t)e * TOK * ID;
#pragma unroll
    for (int mt = 0; mt < 4; mt++) {
        int r0 = m0 + wm + mt * 16 + (lane >> 2);
#pragma unroll
        for (int half = 0; half < 2; half++) {
            int r = r0 + half * 8;
            if (r >= n) continue;
            float sg = g_ag[e * TOK + r] * wsg;
            float su = g_au[e * TOK + r] * wsu;
            float* Hr = H + (size_t)r * ID;
#pragma unroll
            for (int nt = 0; nt < 4; nt++) {
                int c = n0 + wn + nt * 8 + (lane & 3) * 2;
                float2 o;
                float gg0 = clipf((float)cg[mt][nt][half*2+0] * sg, -20.f, 20.f);
                float gg1 = clipf((float)cg[mt][nt][half*2+1] * sg, -20.f, 20.f);
                float uu0 = (float)cu[mt][nt][half*2+0] * su;
                float uu1 = (float)cu[mt][nt][half*2+1] * su;
                o.x = clipf(gg0 * fast_sigmoid(gg0) * uu0, -1000.f, 1000.f);
                o.y = clipf(gg1 * fast_sigmoid(gg1) * uu1, -1000.f, 1000.f);
                *(float2*)(Hr + c) = o;
            }
        }
    }
}

// ---------------- GEMM 2: down, R10 VERBATIM, scatter atomicAdd ----------
// grid (TOK/128, HD/64, NEXP), 128 threads; static smem 2 x 15360 B.
#define D_STG 15360
__global__ __launch_bounds__(128) void k_gemm_d(float* __restrict__ out) {
    int e = blockIdx.z;
    int n = g_cnt[e];
    int m0 = blockIdx.x * 128;
    if (m0 >= n) return;
    int n0 = blockIdx.y * 64;

    __shared__ __align__(16) uint8_t dsm[2 * D_STG];
    uint32_t sb = smem_u32(dsm);

    const int4* A4 = (const int4*)(g_hq + (size_t)e * TOK * ID);
    const int4* B4 = (const int4*)&g_qw[2][e][0];
    const int KI4 = ID / 16;  // 128

    int tid = threadIdx.x;
    int warp = tid >> 5, lane = tid & 31;
    int wm = (warp >> 1) * 64;
    int wn = (warp & 1) * 32;

    int acc[4][4][4] = {};

#define D_ISSUE(kb_) do {                                                     \
        int st_ = (kb_) & 1; uint32_t b_ = sb + st_ * D_STG;                  \
        for (int i = tid; i < 512; i += 128) {                                \
            int row_ = i >> 2, seg_ = i & 3;                                  \
            int grc_ = min(m0 + row_, n - 1);                                 \
            cpa16(b_ + row_ * 80 + seg_ * 16,                                 \
                  A4 + (size_t)grc_ * KI4 + (kb_) * 4 + seg_);               \
        }                                                                     \
        for (int i = tid; i < 256; i += 128) {                                \
            int row_ = i >> 2, seg_ = i & 3;                                  \
            int br_ = n0 + row_;                                              \
            cpa16(b_ + 10240 + row_ * 80 + seg_ * 16,                         \
                  B4 + (size_t)br_ * KI4 + (kb_) * 4 + seg_);                \
        }                                                                     \
    } while (0)

    D_ISSUE(0); CP_COMMIT();
    D_ISSUE(1); CP_COMMIT();

    const int KB = ID / 64;  // 32
    for (int kb = 0; kb < KB; kb++) {
        CP_WAIT1();
        __syncthreads();
        int st = kb & 1;
        const int8_t* pA = (const int8_t*)(dsm + st * D_STG);
        const int8_t* pB = pA + 10240;
#pragma unroll
        for (int ks = 0; ks < 2; ks++) {
            int b[4][2];
#pragma unroll
            for (int nt = 0; nt < 4; nt++)
                load_b_frag(b[nt], pB + (wn + nt * 8) * 80 + ks * 32, lane);
#pragma unroll
            for (int mt = 0; mt < 4; mt++) {
                int a[4];
                load_a_frag(a, pA + (wm + mt * 16) * 80 + ks * 32, lane);
#pragma unroll
                for (int nt = 0; nt < 4; nt++)
                    mma_s8(acc[mt][nt], a, b[nt]);
            }
        }
        __syncthreads();
        if (kb + 2 < KB) D_ISSUE(kb + 2);
        CP_COMMIT();
    }
#undef D_ISSUE

    float wsd = g_wscale[2 * NEXP + e];
#pragma unroll
    for (int mt = 0; mt < 4; mt++) {
        int r0 = m0 + wm + mt * 16 + (lane >> 2);
#pragma unroll
        for (int half = 0; half < 2; half++) {
            int r = r0 + half * 8;
            if (r >= n) continue;
            float s = g_ah[e * TOK + r] * wsd;
            int t = g_lidx[e * TOK + r];
            float lw = g_lw[e * TOK + r];
            float* outr = out + (size_t)t * HD;
#pragma unroll
            for (int nt = 0; nt < 4; nt++) {
                int c = n0 + wn + nt * 8 + (lane & 3) * 2;
                atomicAdd(outr + c,     lw * ((float)acc[mt][nt][half*2+0] * s));
                atomicAdd(outr + c + 1, lw * ((float)acc[mt][nt][half*2+1] * s));
            }
        }
    }
}

__global__ void k_clip(float* out, int n) {
    int i = blockIdx.x * blockDim.x + threadIdx.x;
    if (i < n) out[i] = clipf(out[i], -10000.f, 10000.f);
    if (i < NEXP) g_cnt[i] = 0;    // re-arm expert counters for next replay
}

// ---------------- launcher ----------------
extern "C" void kernel_launch(void* const* d_in, const int* in_sizes, int n_in,
                              void* d_out, int out_size) {
    const float* x   = (const float*)d_in[0];
    const float* rw  = (const float*)d_in[1];
    const float* rb  = (const float*)d_in[2];
    const float* Wg  = (const float*)d_in[3];
    const float* Wu  = (const float*)d_in[4];
    const float* Wd  = (const float*)d_in[5];
    const float* ng  = (const float*)d_in[6];
    const float* nu  = (const float*)d_in[7];
    const float* nd  = (const float*)d_in[8];
    const float* sWg = (const float*)d_in[9];
    const float* sWu = (const float*)d_in[10];
    const float* sWd = (const float*)d_in[11];
    const float* sng = (const float*)d_in[12];
    const float* snu = (const float*)d_in[13];
    const float* snd = (const float*)d_in[14];
    float* out = (float*)d_out;

    float* logits_dst;
    if (out_size >= TOK * HD + TOK * 8) {
        logits_dst = out + (size_t)TOK * HD;
    } else {
        void* p = nullptr;
        cudaGetSymbolAddress(&p, g_logits_scratch);
        logits_dst = (float*)p;
    }

    cudaFuncSetAttribute(k_gemm_gu,
                         cudaFuncAttributeMaxDynamicSharedMemorySize, GU_SMEM);

    // gu GEMM at launch slot #4 (the slot ncu captures)
    k_pre<<<RED_BLK * NMAT + TOK, 256>>>(x, rw, rb, logits_dst, out,
                                         Wg, Wu, Wd, sWg, sWu, sWd);       // 1
    k_wqfin<<<dim3(NW / 4 / 256, NMAT), 256>>>(Wg, Wu, Wd, sWg, sWu, sWd); // 2
    k_xq_all<<<dim3(TOK / 8, NEXP), 256>>>(x, ng, nu, sng, snu);           // 3
    k_gemm_gu<<<dim3(TOK / 128, ID / 64, NEXP), 128, GU_SMEM>>>();         // 4 <- ncu
    k_hq_all<<<dim3(TOK / 8, NEXP), 256>>>(nd, snd);                       // 5
    k_gemm_d<<<dim3(TOK / 128, HD / 64, NEXP), 128>>>(out);                // 6
    k_clip<<<(TOK * HD + 255) / 256, 256>>>(out, TOK * HD);                // 7
}

// round 17
// speedup vs baseline: 1.6085x; 1.1146x over previous
#include <cuda_runtime.h>
#include <math.h>
#include <stdint.h>

// BitNet MoE layer, GB300.  FINAL = R10 exactly as benched at 1847.4us.
// R16 isolated the launch fusions as a +207us regression (GEMMs identical,
// tensor pipe 92.1% both rounds), so this reverts to the champion source
// byte-for-byte: separate wred/wfin/wq weight-quant chain, fused
// router+lists+zero, warp-per-row xq/hq, and the 128-thread 128x64-tile
// mma.sync GEMMs with 2-stage cp.async (legacy-IMMA ceiling on sm_103a;
// tcgen05 is compiler-gated off, dp4a hybrids are smem-crossbar-capped).

#define TOK  8192
#define HD   768
#define ID   2048
#define NEXP 9
#define NMAT 27
#define NW   (ID*HD)
#define RED_BLK 64

// ---------------- scratch (device globals; allocation-free) ----------------
__device__ __align__(16) int8_t g_qw[3][NEXP][NW];            // {-1,0,1}
__device__ double g_part[NMAT * RED_BLK * 2];
__device__ double g_mean[NMAT];
__device__ float  g_wscale[NMAT];
__device__ float  g_logits_scratch[TOK * 8];
__device__ int    g_cnt[NEXP];                                 // zeroed by k_wred_all/k_clip
__device__ int    g_lidx[NEXP * TOK];
__device__ float  g_lw[NEXP * TOK];
__device__ __align__(16) int8_t g_xg[(size_t)NEXP * TOK * HD];
__device__ __align__(16) int8_t g_xu[(size_t)NEXP * TOK * HD];
__device__ float  g_ag[NEXP * TOK], g_au[NEXP * TOK], g_ah[NEXP * TOK];
__device__ __align__(16) float  g_hidden[(size_t)NEXP * TOK * ID];
__device__ __align__(16) int8_t g_hq[(size_t)NEXP * TOK * ID];

__device__ __forceinline__ float clipf(float v, float lo, float hi) {
    return fminf(fmaxf(v, lo), hi);
}

__device__ __forceinline__ float fast_sigmoid(float g) {
    float ax = fabsf(g);
    float z  = -1.4426950408889634f * ax;
    float nf = rintf(z);
    float f  = z - nf;
    float p  = 1.5403530e-4f;
    p = fmaf(p, f, 1.33335581e-3f);
    p = fmaf(p, f, 9.61812911e-3f);
    p = fmaf(p, f, 5.55041087e-2f);
    p = fmaf(p, f, 2.40226507e-1f);
    p = fmaf(p, f, 6.93147181e-1f);
    p = fmaf(p, f, 1.0f);
    float s = __int_as_float(((int)nf + 127) << 23);
    float t = p * s;
    float d = 1.0f + t;
    float r = __int_as_float(0x7EF311C3 - __float_as_int(d));
    r = r * (2.0f - d * r);
    r = r * (2.0f - d * r);
    r = r * (2.0f - d * r);
    return (g >= 0.f) ? r : 1.0f - r;
}

__device__ __forceinline__ uint32_t smem_u32(const void* p) {
    uint32_t a;
    asm("{ .reg .u64 t; cvta.to.shared.u64 t, %1; cvt.u32.u64 %0, t; }"
        : "=r"(a) : "l"(p));
    return a;
}
__device__ __forceinline__ void cpa16(uint32_t dst, const void* src) {
    asm volatile("cp.async.cg.shared.global [%0], [%1], 16;"
                 :: "r"(dst), "l"(src) : "memory");
}
#define CP_COMMIT() asm volatile("cp.async.commit_group;" ::: "memory")
#define CP_WAIT1()  asm volatile("cp.async.wait_group 1;" ::: "memory")

__device__ __forceinline__ void mma_s8(int* c, const int* a, const int* b) {
    asm volatile(
        "mma.sync.aligned.m16n8k32.row.col.s32.s8.s8.s32 "
        "{%0,%1,%2,%3}, {%4,%5,%6,%7}, {%8,%9}, {%0,%1,%2,%3};"
        : "+r"(c[0]), "+r"(c[1]), "+r"(c[2]), "+r"(c[3])
        : "r"(a[0]), "r"(a[1]), "r"(a[2]), "r"(a[3]), "r"(b[0]), "r"(b[1]));
}
__device__ __forceinline__ void load_a_frag(int* a, const int8_t* smem_row0,
                                            int stride, int lane) {
    const int8_t* p = smem_row0 + (lane >> 2) * stride + (lane & 3) * 4;
    a[0] = *(const int*)(p);
    a[1] = *(const int*)(p + 8 * stride);
    a[2] = *(const int*)(p + 16);
    a[3] = *(const int*)(p + 8 * stride + 16);
}
__device__ __forceinline__ void load_b_frag(int* b, const int8_t* smem_row0,
                                            int stride, int lane) {
    const int8_t* p = smem_row0 + (lane >> 2) * stride + (lane & 3) * 4;
    b[0] = *(const int*)(p);
    b[1] = *(const int*)(p + 16);
}

// ---------------- weight quantization ----------------
__global__ __launch_bounds__(256) void k_wred_all(
    const float* __restrict__ Wg, const float* __restrict__ Wu,
    const float* __restrict__ Wd, const float* __restrict__ sWg,
    const float* __restrict__ sWu, const float* __restrict__ sWd) {
    int m = blockIdx.y;
    int kind = m / NEXP, e = m % NEXP;
    const float* base =
        (kind == 0) ? ((e < 8) ? Wg + (size_t)e * NW : sWg)
      : (kind == 1) ? ((e < 8) ? Wu + (size_t)e * NW : sWu)
                    : ((e < 8) ? Wd + (size_t)e * NW : sWd);
    const float4* w4 = (const float4*)base;
    const int N4 = NW / 4;
    int tid = threadIdx.x;
    if (blockIdx.x == 0 && m == 0 && tid < NEXP) g_cnt[tid] = 0;  // fused init
    float s = 0.f, a = 0.f;
    for (int i = blockIdx.x * 256 + tid; i < N4; i += RED_BLK * 256) {
        float4 v = w4[i];
        s += (v.x + v.y) + (v.z + v.w);
        a += (fabsf(v.x) + fabsf(v.y)) + (fabsf(v.z) + fabsf(v.w));
    }
    __shared__ double ss[256], sa[256];
    ss[tid] = (double)s; sa[tid] = (double)a;
    __syncthreads();
    for (int o = 128; o; o >>= 1) {
        if (tid < o) { ss[tid] += ss[tid + o]; sa[tid] += sa[tid + o]; }
        __syncthreads();
    }
    if (tid == 0) {
        g_part[(m * RED_BLK + blockIdx.x) * 2 + 0] = ss[0];
        g_part[(m * RED_BLK + blockIdx.x) * 2 + 1] = sa[0];
    }
}

__global__ void k_wfin() {
    int m = blockIdx.x, tid = threadIdx.x;   // RED_BLK threads
    __shared__ double ss[RED_BLK], sa[RED_BLK];
    ss[tid] = g_part[(m * RED_BLK + tid) * 2 + 0];
    sa[tid] = g_part[(m * RED_BLK + tid) * 2 + 1];
    __syncthreads();
    for (int o = RED_BLK / 2; o; o >>= 1) {
        if (tid < o) { ss[tid] += ss[tid + o]; sa[tid] += sa[tid + o]; }
        __syncthreads();
    }
    if (tid == 0) {
        g_mean[m] = ss[0] / (double)NW;
        double sc = sa[0] / (double)NW;
        if (sc < 1e-8) sc = 1e-8;
        g_wscale[m] = (float)sc;
    }
}

__global__ __launch_bounds__(256) void k_wq_all(
    const float* __restrict__ Wg, const float* __restrict__ Wu,
    const float* __restrict__ Wd, const float* __restrict__ sWg,
    const float* __restrict__ sWu, const float* __restrict__ sWd) {
    int m = blockIdx.y;
    int kind = m / NEXP, e = m % NEXP;
    const float* base =
        (kind == 0) ? ((e < 8) ? Wg + (size_t)e * NW : sWg)
      : (kind == 1) ? ((e < 8) ? Wu + (size_t)e * NW : sWu)
                    : ((e < 8) ? Wd + (size_t)e * NW : sWd);
    int i = blockIdx.x * 256 + threadIdx.x;
    const int N4 = NW / 4;
    if (i >= N4) return;
    float mean = (float)g_mean[m];
    float4 v = ((const float4*)base)[i];
    char4 q;
    q.x = (v.x > mean) ? 1 : ((v.x < mean) ? -1 : 0);
    q.y = (v.y > mean) ? 1 : ((v.y < mean) ? -1 : 0);
    q.z = (v.z > mean) ? 1 : ((v.z < mean) ? -1 : 0);
    q.w = (v.w > mean) ? 1 : ((v.w < mean) ? -1 : 0);
    ((char4*)&g_qw[kind][e][0])[i] = q;
}

// ---------------- router + top2 lists + out-zeroing (fused) ----------------
__global__ __launch_bounds__(128) void k_router_lists(const float* __restrict__ x,
                                                      const float* __restrict__ rw,
                                                      const float* __restrict__ rb,
                                                      float* __restrict__ logits_out,
                                                      float* __restrict__ out) {
    int t = blockIdx.x, tid = threadIdx.x;
    for (int j = tid; j < HD; j += 128) out[(size_t)t * HD + j] = 0.f;
    const float* xr = x + (size_t)t * HD;
    float acc[8];
#pragma unroll
    for (int e = 0; e < 8; e++) acc[e] = 0.f;
    for (int h = tid; h < HD; h += 128) {
        float xv = xr[h];
#pragma unroll
        for (int e = 0; e < 8; e++) acc[e] += xv * rw[e * HD + h];
    }
    __shared__ float s[8][128];
#pragma unroll
    for (int e = 0; e < 8; e++) s[e][tid] = acc[e];
    __syncthreads();
    for (int o = 64; o; o >>= 1) {
        if (tid < o) {
#pragma unroll
            for (int e = 0; e < 8; e++) s[e][tid] += s[e][tid + o];
        }
        __syncthreads();
    }
    if (tid == 0) {
        float l[8], p[8];
        float mx = -1e30f;
#pragma unroll
        for (int e = 0; e < 8; e++) {
            l[e] = s[e][0] + rb[e];
            logits_out[t * 8 + e] = l[e];
            mx = fmaxf(mx, l[e]);
        }
        float ps = 0.f;
#pragma unroll
        for (int e = 0; e < 8; e++) { p[e] = expf(l[e] - mx); ps += p[e]; }
#pragma unroll
        for (int e = 0; e < 8; e++) p[e] /= ps;
        int i1 = 0;
#pragma unroll
        for (int e = 1; e < 8; e++) if (p[e] > p[i1]) i1 = e;
        int i2 = -1;
#pragma unroll
        for (int e = 0; e < 8; e++) {
            if (e == i1) continue;
            if (i2 < 0 || p[e] > p[i2]) i2 = e;
        }
        float den = p[i1] + p[i2] + 1e-8f;
        int p1 = atomicAdd(&g_cnt[i1], 1);
        g_lidx[i1 * TOK + p1] = t;
        g_lw[i1 * TOK + p1] = p[i1] / den;
        int p2 = atomicAdd(&g_cnt[i2], 1);
        g_lidx[i2 * TOK + p2] = t;
        g_lw[i2 * TOK + p2] = p[i2] / den;
        g_lidx[8 * TOK + t] = t;
        g_lw[8 * TOK + t] = 1.f;
        if (t == 0) g_cnt[8] = TOK;
    }
}

// ---------------- input rmsnorm + act quant: warp per row ----------------
__global__ __launch_bounds__(256) void k_xq_all(const float* __restrict__ x,
                                                const float* __restrict__ ng,
                                                const float* __restrict__ nu,
                                                const float* __restrict__ sng,
                                                const float* __restrict__ snu) {
    int e = blockIdx.y;
    int wid = threadIdx.x >> 5, lane = threadIdx.x & 31;
    int r = blockIdx.x * 8 + wid;
    if (r >= g_cnt[e]) return;
    const float* nwg = (e < 8) ? ng + (size_t)e * HD : sng;
    const float* nwu = (e < 8) ? nu + (size_t)e * HD : snu;
    int t = g_lidx[e * TOK + r];
    const float4* xr4 = (const float4*)(x + (size_t)t * HD);
    const float4* ng4 = (const float4*)nwg;
    const float4* nu4 = (const float4*)nwu;

    float v[24], gw[24], uw[24];
    float ssum = 0.f;
#pragma unroll
    for (int i = 0; i < 6; i++) {
        float4 w = xr4[lane + i * 32];
        float4 a = ng4[lane + i * 32];
        float4 b = nu4[lane + i * 32];
        float c0 = clipf(w.x, -100.f, 100.f), c1 = clipf(w.y, -100.f, 100.f);
        float c2 = clipf(w.z, -100.f, 100.f), c3 = clipf(w.w, -100.f, 100.f);
        v[i*4+0] = c0; v[i*4+1] = c1; v[i*4+2] = c2; v[i*4+3] = c3;
        ssum += c0*c0 + c1*c1 + c2*c2 + c3*c3;
        gw[i*4+0] = a.x; gw[i*4+1] = a.y; gw[i*4+2] = a.z; gw[i*4+3] = a.w;
        uw[i*4+0] = b.x; uw[i*4+1] = b.y; uw[i*4+2] = b.z; uw[i*4+3] = b.w;
    }
#pragma unroll
    for (int o = 16; o; o >>= 1) ssum += __shfl_xor_sync(0xFFFFFFFFu, ssum, o);
    float var = fmaxf(ssum / (float)HD, 1e-5f);
    float rinv = 1.f / sqrtf(var + 1e-5f);

    float mg = 0.f, mu = 0.f;
#pragma unroll
    for (int i = 0; i < 24; i++) {
        float xh = clipf(v[i] * rinv, -10.f, 10.f);
        float vg = clipf(gw[i] * xh, -50.f, 50.f);
        float vu = clipf(uw[i] * xh, -50.f, 50.f);
        gw[i] = vg; uw[i] = vu;
        mg = fmaxf(mg, fabsf(vg));
        mu = fmaxf(mu, fabsf(vu));
    }
#pragma unroll
    for (int o = 16; o; o >>= 1) {
        mg = fmaxf(mg, __shfl_xor_sync(0xFFFFFFFFu, mg, o));
        mu = fmaxf(mu, __shfl_xor_sync(0xFFFFFFFFu, mu, o));
    }
    mg = fmaxf(mg, 1e-4f); mu = fmaxf(mu, 1e-4f);
    if (lane == 0) { g_ag[e * TOK + r] = mg / 127.f; g_au[e * TOK + r] = mu / 127.f; }
    float scg = 127.f / mg, scu = 127.f / mu;
    size_t rowoff = ((size_t)e * TOK + r) * HD;
    char4* og = (char4*)(g_xg + rowoff);
    char4* ou = (char4*)(g_xu + rowoff);
#pragma unroll
    for (int i = 0; i < 6; i++) {
        char4 qg, qu;
        int q;
        q = (int)rintf(gw[i*4+0] * scg); qg.x = (char)max(-128, min(127, q));
        q = (int)rintf(gw[i*4+1] * scg); qg.y = (char)max(-128, min(127, q));
        q = (int)rintf(gw[i*4+2] * scg); qg.z = (char)max(-128, min(127, q));
        q = (int)rintf(gw[i*4+3] * scg); qg.w = (char)max(-128, min(127, q));
        q = (int)rintf(uw[i*4+0] * scu); qu.x = (char)max(-128, min(127, q));
        q = (int)rintf(uw[i*4+1] * scu); qu.y = (char)max(-128, min(127, q));
        q = (int)rintf(uw[i*4+2] * scu); qu.z = (char)max(-128, min(127, q));
        q = (int)rintf(uw[i*4+3] * scu); qu.w = (char)max(-128, min(127, q));
        og[lane + i * 32] = qg;
        ou[lane + i * 32] = qu;
    }
}

// ---------------- hidden rmsnorm + quant: warp per row -------------------
__global__ __launch_bounds__(256) void k_hq_all(const float* __restrict__ nd,
                                                const float* __restrict__ snd) {
    int e = blockIdx.y;
    int wid = threadIdx.x >> 5, lane = threadIdx.x & 31;
    int r = blockIdx.x * 8 + wid;
    if (r >= g_cnt[e]) return;
    const float* nw = (e < 8) ? nd + (size_t)e * ID : snd;
    size_t rowoff = ((size_t)e * TOK + r) * ID;
    const float4* hr4 = (const float4*)(g_hidden + rowoff);
    const float4* nw4 = (const float4*)nw;

    float v[64];
    float ssum = 0.f;
#pragma unroll
    for (int i = 0; i < 16; i++) {
        float4 w = hr4[lane + i * 32];
        float c0 = clipf(w.x, -100.f, 100.f), c1 = clipf(w.y, -100.f, 100.f);
        float c2 = clipf(w.z, -100.f, 100.f), c3 = clipf(w.w, -100.f, 100.f);
        v[i*4+0] = c0; v[i*4+1] = c1; v[i*4+2] = c2; v[i*4+3] = c3;
        ssum += c0*c0 + c1*c1 + c2*c2 + c3*c3;
    }
#pragma unroll
    for (int o = 16; o; o >>= 1) ssum += __shfl_xor_sync(0xFFFFFFFFu, ssum, o);
    float var = fmaxf(ssum / (float)ID, 1e-5f);
    float rinv = 1.f / sqrtf(var + 1e-5f);

    float m = 0.f;
#pragma unroll
    for (int i = 0; i < 16; i++) {
        float4 a = nw4[lane + i * 32];
        float xh0 = clipf(v[i*4+0] * rinv, -10.f, 10.f);
        float xh1 = clipf(v[i*4+1] * rinv, -10.f, 10.f);
        float xh2 = clipf(v[i*4+2] * rinv, -10.f, 10.f);
        float xh3 = clipf(v[i*4+3] * rinv, -10.f, 10.f);
        v[i*4+0] = clipf(a.x * xh0, -50.f, 50.f);
        v[i*4+1] = clipf(a.y * xh1, -50.f, 50.f);
        v[i*4+2] = clipf(a.z * xh2, -50.f, 50.f);
        v[i*4+3] = clipf(a.w * xh3, -50.f, 50.f);
        m = fmaxf(m, fmaxf(fmaxf(fabsf(v[i*4+0]), fabsf(v[i*4+1])),
                           fmaxf(fabsf(v[i*4+2]), fabsf(v[i*4+3]))));
    }
#pragma unroll
    for (int o = 16; o; o >>= 1) m = fmaxf(m, __shfl_xor_sync(0xFFFFFFFFu, m, o));
    m = fmaxf(m, 1e-4f);
    if (lane == 0) g_ah[e * TOK + r] = m / 127.f;
    float sc = 127.f / m;
    char4* oq = (char4*)(g_hq + rowoff);
#pragma unroll
    for (int i = 0; i < 16; i++) {
        char4 q4;
        int q;
        q = (int)rintf(v[i*4+0] * sc); q4.x = (char)max(-128, min(127, q));
        q = (int)rintf(v[i*4+1] * sc); q4.y = (char)max(-128, min(127, q));
        q = (int)rintf(v[i*4+2] * sc); q4.z = (char)max(-128, min(127, q));
        q = (int)rintf(v[i*4+3] * sc); q4.w = (char)max(-128, min(127, q));
        oq[lane + i * 32] = q4;
    }
}

// ---------------- GEMM 1: gate+up, cp.async double-buffered --------------
// grid (TOK/128, ID/64, NEXP), 128 threads; dyn smem 2 stages x 30720 B.
#define GU_STG 30720
#define GU_SMEM (2 * GU_STG)
__global__ __launch_bounds__(128) void k_gemm_gu_mma() {
    int e = blockIdx.z;
    int n = g_cnt[e];
    int m0 = blockIdx.x * 128;
    if (m0 >= n) return;
    int n0 = blockIdx.y * 64;

    extern __shared__ __align__(16) uint8_t dsm[];
    uint32_t sb = smem_u32(dsm);

    const int4* Ag4 = (const int4*)(g_xg + (size_t)e * TOK * HD);
    const int4* Au4 = (const int4*)(g_xu + (size_t)e * TOK * HD);
    const int4* Bg4 = (const int4*)&g_qw[0][e][0];
    const int4* Bu4 = (const int4*)&g_qw[1][e][0];
    const int KI4 = HD / 16;  // 48

    int tid = threadIdx.x;
    int warp = tid >> 5, lane = tid & 31;
    int wm = (warp >> 1) * 64;
    int wn = (warp & 1) * 32;

    int cg[4][4][4] = {};
    int cu[4][4][4] = {};

#define GU_ISSUE(kb_) do {                                                    \
        int st_ = (kb_) & 1; uint32_t b_ = sb + st_ * GU_STG;                 \
        for (int i = tid; i < 512; i += 128) {                                \
            int row_ = i >> 2, seg_ = i & 3;                                  \
            int grc_ = min(m0 + row_, n - 1);                                 \
            uint32_t d_ = b_ + row_ * 80 + seg_ * 16;                         \
            cpa16(d_,         Ag4 + (size_t)grc_ * KI4 + (kb_) * 4 + seg_);  \
            cpa16(d_ + 10240, Au4 + (size_t)grc_ * KI4 + (kb_) * 4 + seg_);  \
        }                                                                     \
        for (int i = tid; i < 256; i += 128) {                                \
            int row_ = i >> 2, seg_ = i & 3;                                  \
            int br_ = n0 + row_;                                              \
            uint32_t d_ = b_ + 20480 + row_ * 80 + seg_ * 16;                 \
            cpa16(d_,        Bg4 + (size_t)br_ * KI4 + (kb_) * 4 + seg_);    \
            cpa16(d_ + 5120, Bu4 + (size_t)br_ * KI4 + (kb_) * 4 + seg_);    \
        }                                                                     \
    } while (0)

    GU_ISSUE(0); CP_COMMIT();
    GU_ISSUE(1); CP_COMMIT();

    const int KB = HD / 64;  // 12
    for (int kb = 0; kb < KB; kb++) {
        CP_WAIT1();
        __syncthreads();
        int st = kb & 1;
        const int8_t* pAg = (const int8_t*)(dsm + st * GU_STG);
        const int8_t* pAu = pAg + 10240;
        const int8_t* pBg = pAg + 20480;
        const int8_t* pBu = pAg + 25600;
#pragma unroll
        for (int ks = 0; ks < 2; ks++) {
            int bg[4][2], bu[4][2];
#pragma unroll
            for (int nt = 0; nt < 4; nt++) {
                load_b_frag(bg[nt], pBg + (wn + nt * 8) * 80 + ks * 32, 80, lane);
                load_b_frag(bu[nt], pBu + (wn + nt * 8) * 80 + ks * 32, 80, lane);
            }
#pragma unroll
            for (int mt = 0; mt < 4; mt++) {
                int ag[4], au[4];
                load_a_frag(ag, pAg + (wm + mt * 16) * 80 + ks * 32, 80, lane);
                load_a_frag(au, pAu + (wm + mt * 16) * 80 + ks * 32, 80, lane);
#pragma unroll
                for (int nt = 0; nt < 4; nt++) {
                    mma_s8(cg[mt][nt], ag, bg[nt]);
                    mma_s8(cu[mt][nt], au, bu[nt]);
                }
            }
        }
        __syncthreads();
        if (kb + 2 < KB) GU_ISSUE(kb + 2);
        CP_COMMIT();
    }
#undef GU_ISSUE

    float wsg = g_wscale[0 * NEXP + e];
    float wsu = g_wscale[1 * NEXP + e];
    float* H = g_hidden + (size_t)e * TOK * ID;
#pragma unroll
    for (int mt = 0; mt < 4; mt++) {
        int r0 = m0 + wm + mt * 16 + (lane >> 2);
#pragma unroll
        for (int half = 0; half < 2; half++) {
            int r = r0 + half * 8;
            if (r >= n) continue;
            float sg = g_ag[e * TOK + r] * wsg;
            float su = g_au[e * TOK + r] * wsu;
            float* Hr = H + (size_t)r * ID;
#pragma unroll
            for (int nt = 0; nt < 4; nt++) {
                int c = n0 + wn + nt * 8 + (lane & 3) * 2;
#pragma unroll
                for (int cc = 0; cc < 2; cc++) {
                    int gi = cg[mt][nt][half * 2 + cc];
                    int ui = cu[mt][nt][half * 2 + cc];
                    float gg = clipf((float)gi * sg, -20.f, 20.f);
                    float uu = (float)ui * su;
                    float h = gg * fast_sigmoid(gg) * uu;
                    Hr[c + cc] = clipf(h, -1000.f, 1000.f);
                }
            }
        }
    }
}

// ---------------- GEMM 2: down, cp.async double-buffered, scatter --------
// grid (TOK/128, HD/64, NEXP), 128 threads; static smem 2 x 15360 B.
#define D_STG 15360
__global__ __launch_bounds__(128) void k_gemm_d_mma(float* __restrict__ out) {
    int e = blockIdx.z;
    int n = g_cnt[e];
    int m0 = blockIdx.x * 128;
    if (m0 >= n) return;
    int n0 = blockIdx.y * 64;

    __shared__ __align__(16) uint8_t dsm[2 * D_STG];
    uint32_t sb = smem_u32(dsm);

    const int4* A4 = (const int4*)(g_hq + (size_t)e * TOK * ID);
    const int4* B4 = (const int4*)&g_qw[2][e][0];
    const int KI4 = ID / 16;  // 128

    int tid = threadIdx.x;
    int warp = tid >> 5, lane = tid & 31;
    int wm = (warp >> 1) * 64;
    int wn = (warp & 1) * 32;

    int acc[4][4][4] = {};

#define D_ISSUE(kb_) do {                                                     \
        int st_ = (kb_) & 1; uint32_t b_ = sb + st_ * D_STG;                  \
        for (int i = tid; i < 512; i += 128) {                                \
            int row_ = i >> 2, seg_ = i & 3;                                  \
            int grc_ = min(m0 + row_, n - 1);                                 \
            cpa16(b_ + row_ * 80 + seg_ * 16,                                 \
                  A4 + (size_t)grc_ * KI4 + (kb_) * 4 + seg_);               \
        }                                                                     \
        for (int i = tid; i < 256; i += 128) {                                \
            int row_ = i >> 2, seg_ = i & 3;                                  \
            int br_ = n0 + row_;                                              \
            cpa16(b_ + 10240 + row_ * 80 + seg_ * 16,                         \
                  B4 + (size_t)br_ * KI4 + (kb_) * 4 + seg_);                \
        }                                                                     \
    } while (0)

    D_ISSUE(0); CP_COMMIT();
    D_ISSUE(1); CP_COMMIT();

    const int KB = ID / 64;  // 32
    for (int kb = 0; kb < KB; kb++) {
        CP_WAIT1();
        __syncthreads();
        int st = kb & 1;
        const int8_t* pA = (const int8_t*)(dsm + st * D_STG);
        const int8_t* pB = pA + 10240;
#pragma unroll
        for (int ks = 0; ks < 2; ks++) {
            int b[4][2];
#pragma unroll
            for (int nt = 0; nt < 4; nt++)
                load_b_frag(b[nt], pB + (wn + nt * 8) * 80 + ks * 32, 80, lane);
#pragma unroll
            for (int mt = 0; mt < 4; mt++) {
                int a[4];
                load_a_frag(a, pA + (wm + mt * 16) * 80 + ks * 32, 80, lane);
#pragma unroll
                for (int nt = 0; nt < 4; nt++)
                    mma_s8(acc[mt][nt], a, b[nt]);
            }
        }
        __syncthreads();
        if (kb + 2 < KB) D_ISSUE(kb + 2);
        CP_COMMIT();
    }
#undef D_ISSUE

    float wsd = g_wscale[2 * NEXP + e];
#pragma unroll
    for (int mt = 0; mt < 4; mt++) {
        int r0 = m0 + wm + mt * 16 + (lane >> 2);
#pragma unroll
        for (int half = 0; half < 2; half++) {
            int r = r0 + half * 8;
            if (r >= n) continue;
            float s = g_ah[e * TOK + r] * wsd;
            int t = g_lidx[e * TOK + r];
            float lw = g_lw[e * TOK + r];
            float* outr = out + (size_t)t * HD;
#pragma unroll
            for (int nt = 0; nt < 4; nt++) {
                int c = n0 + wn + nt * 8 + (lane & 3) * 2;
#pragma unroll
                for (int cc = 0; cc < 2; cc++) {
                    float y = lw * ((float)acc[mt][nt][half * 2 + cc] * s);
                    atomicAdd(outr + c + cc, y);
                }
            }
        }
    }
}

__global__ void k_clip(float* out, int n) {
    int i = blockIdx.x * blockDim.x + threadIdx.x;
    if (i < n) out[i] = clipf(out[i], -10000.f, 10000.f);
}

// ---------------- launcher ----------------
extern "C" void kernel_launch(void* const* d_in, const int* in_sizes, int n_in,
                              void* d_out, int out_size) {
    const float* x   = (const float*)d_in[0];
    const float* rw  = (const float*)d_in[1];
    const float* rb  = (const float*)d_in[2];
    const float* Wg  = (const float*)d_in[3];
    const float* Wu  = (const float*)d_in[4];
    const float* Wd  = (const float*)d_in[5];
    const float* ng  = (const float*)d_in[6];
    const float* nu  = (const float*)d_in[7];
    const float* nd  = (const float*)d_in[8];
    const float* sWg = (const float*)d_in[9];
    const float* sWu = (const float*)d_in[10];
    const float* sWd = (const float*)d_in[11];
    const float* sng = (const float*)d_in[12];
    const float* snu = (const float*)d_in[13];
    const float* snd = (const float*)d_in[14];
    float* out = (float*)d_out;

    float* logits_dst;
    if (out_size >= TOK * HD + TOK * 8) {
        logits_dst = out + (size_t)TOK * HD;
    } else {
        void* p = nullptr;
        cudaGetSymbolAddress(&p, g_logits_scratch);
        logits_dst = (float*)p;
    }

    cudaFuncSetAttribute(k_gemm_gu_mma,
                         cudaFuncAttributeMaxDynamicSharedMemorySize, GU_SMEM);

    k_wred_all<<<dim3(RED_BLK, NMAT), 256>>>(Wg, Wu, Wd, sWg, sWu, sWd);   // 1
    k_wfin<<<NMAT, RED_BLK>>>();                                           // 2
    k_wq_all<<<dim3(NW / 4 / 256, NMAT), 256>>>(Wg, Wu, Wd, sWg, sWu, sWd);// 3
    k_router_lists<<<TOK, 128>>>(x, rw, rb, logits_dst, out);              // 4
    k_xq_all<<<dim3(TOK / 8, NEXP), 256>>>(x, ng, nu, sng, snu);           // 5
    k_gemm_gu_mma<<<dim3(TOK / 128, ID / 64, NEXP), 128, GU_SMEM>>>();     // 6
    k_hq_all<<<dim3(TOK / 8, NEXP), 256>>>(nd, snd);                       // 7
    k_gemm_d_mma<<<dim3(TOK / 128, HD / 64, NEXP), 128>>>(out);            // 8
    k_clip<<<(TOK * HD + 255) / 256, 256>>>(out, TOK * HD);                // 9
}